// round 3
// baseline (speedup 1.0000x reference)
#include <cuda_runtime.h>
#include <cuda_bf16.h>

// Chamfer distance via uniform spatial grid, B=2, N=M=8192, C=3, coords ~U[0,1).
// Pipeline (all graph-capturable, no allocation, static scratch):
//   1. zero cell counts
//   2. count points per cell (atomicAdd; counts deterministic)
//   3. per-set exclusive scan -> (start,count) ranges + scatter cursors
//   4. scatter points to cell-sorted order (float4 xyz+norm) + original index
//   5. query: for each sorted query, scan 3x3x3 ring (expand if needed),
//      min of (||t||^2 - 2 q.t); write dist to g_dist[original index]
//      (min is permutation-invariant -> bitwise deterministic output)
//   6. per-(dir,batch) fixed-order sum -> partials
//   7. finalize scalar
//
// d(q,t) = ||q||^2 + (||t||^2 - 2 q.t)

#define G        16
#define NC       (G * G * G)          // 4096 cells
#define B_MAX    4
#define NSETS    (2 * B_MAX)          // cloud * B + b
#define NPTS_MAX 8192
#define QBLOCK   128
#define RBLOCK   256

__device__ int    g_count [NSETS * NC];
__device__ int2   g_range [NSETS * NC];      // (start, count)
__device__ int    g_cursor[NSETS * NC];
__device__ float4 g_sorted[NSETS * NPTS_MAX]; // x,y,z,||p||^2  (cell-sorted)
__device__ int    g_sidx  [NSETS * NPTS_MAX]; // original index
__device__ float  g_dist  [NSETS * NPTS_MAX]; // [yb][orig index]
__device__ float  g_partials[NSETS * 64];

__device__ __forceinline__ int cell_of(float v) {
    int c = (int)(v * (float)G);
    return min(max(c, 0), G - 1);
}

__global__ void zero_kernel(int n) {
    int i = blockIdx.x * blockDim.x + threadIdx.x;
    if (i < n) g_count[i] = 0;
}

__global__ void count_kernel(const float* __restrict__ pos,
                             const float* __restrict__ xhat,
                             int N, int M, int B) {
    const int sid   = blockIdx.y;
    const int cloud = sid / B;
    const int b     = sid % B;
    const int n     = cloud ? M : N;
    const float* P  = cloud ? xhat : pos;
    const int i = blockIdx.x * blockDim.x + threadIdx.x;
    if (i >= n) return;
    const float* p = P + ((size_t)b * n + i) * 3;
    const int cell = (cell_of(p[2]) * G + cell_of(p[1])) * G + cell_of(p[0]);
    atomicAdd(&g_count[sid * NC + cell], 1);
}

#define SCAN_T 1024
#define CPT    (NC / SCAN_T)   // 4 cells per thread
__global__ __launch_bounds__(SCAN_T)
void scan_kernel() {
    const int sid  = blockIdx.x;
    const int base = sid * NC;
    const int tid  = threadIdx.x;
    int c[CPT];
    int tsum = 0;
#pragma unroll
    for (int j = 0; j < CPT; ++j) { c[j] = g_count[base + tid * CPT + j]; tsum += c[j]; }
    __shared__ int sc[SCAN_T];
    sc[tid] = tsum;
    __syncthreads();
    for (int off = 1; off < SCAN_T; off <<= 1) {
        int v = (tid >= off) ? sc[tid - off] : 0;
        __syncthreads();
        sc[tid] += v;
        __syncthreads();
    }
    int run = sc[tid] - tsum;   // exclusive prefix
#pragma unroll
    for (int j = 0; j < CPT; ++j) {
        g_range [base + tid * CPT + j] = make_int2(run, c[j]);
        g_cursor[base + tid * CPT + j] = run;
        run += c[j];
    }
}

__global__ void scatter_kernel(const float* __restrict__ pos,
                               const float* __restrict__ xhat,
                               int N, int M, int B) {
    const int sid   = blockIdx.y;
    const int cloud = sid / B;
    const int b     = sid % B;
    const int n     = cloud ? M : N;
    const float* P  = cloud ? xhat : pos;
    const int i = blockIdx.x * blockDim.x + threadIdx.x;
    if (i >= n) return;
    const float* p = P + ((size_t)b * n + i) * 3;
    const float x = p[0], y = p[1], z = p[2];
    const int cell = (cell_of(z) * G + cell_of(y)) * G + cell_of(x);
    const int idx  = atomicAdd(&g_cursor[sid * NC + cell], 1);
    g_sorted[sid * NPTS_MAX + idx] = make_float4(x, y, z, x * x + y * y + z * z);
    g_sidx  [sid * NPTS_MAX + idx] = i;
}

__global__ __launch_bounds__(QBLOCK)
void query_kernel(int N, int M, int B) {
    const int yb  = blockIdx.y;        // dir*B + b
    const int dir = yb / B;
    const int b   = yb % B;
    const int nQ  = dir ? M : N;
    const int sid_q = dir * B + b;            // queries: cloud == dir
    const int sid_t = (1 - dir) * B + b;      // targets: other cloud
    const int i = blockIdx.x * blockDim.x + threadIdx.x;
    if (i >= nQ) return;

    const float4 qf = g_sorted[sid_q * NPTS_MAX + i];
    const int    oi = g_sidx  [sid_q * NPTS_MAX + i];
    const float m2x = -2.0f * qf.x;
    const float m2y = -2.0f * qf.y;
    const float m2z = -2.0f * qf.z;
    const float qn  = qf.w;
    const int cx = cell_of(qf.x), cy = cell_of(qf.y), cz = cell_of(qf.z);

    const int2*   __restrict__ range = g_range  + sid_t * NC;
    const float4* __restrict__ pts   = g_sorted + sid_t * NPTS_MAX;

    const float h = 1.0f / (float)G;
    float minAcc = 3.4e38f;
    int r = 1;

    while (true) {
        const int x0 = max(cx - r, 0), x1 = min(cx + r, G - 1);
        const int y0 = max(cy - r, 0), y1 = min(cy + r, G - 1);
        const int z0 = max(cz - r, 0), z1 = min(cz + r, G - 1);

        for (int z = z0; z <= z1; ++z) {
            const int dz = abs(z - cz);
            for (int y = y0; y <= y1; ++y) {
                const int dyz = max(abs(y - cy), dz);
                const int rowbase = (z * G + y) * G;
                if (r > 1 && dyz < r) {
                    // interior rows already scanned; only the two x extremes are new
#pragma unroll
                    for (int t = 0; t < 2; ++t) {
                        const int x = (t == 0) ? (cx - r) : (cx + r);
                        if (x < 0 || x > G - 1) continue;
                        const int2 rg = range[rowbase + x];
                        for (int k = 0; k < rg.y; ++k) {
                            const float4 tt = pts[rg.x + k];
                            const float d = fmaf(m2x, tt.x,
                                            fmaf(m2y, tt.y,
                                            fmaf(m2z, tt.z, tt.w)));
                            minAcc = fminf(minAcc, d);
                        }
                    }
                } else {
                    for (int x = x0; x <= x1; ++x) {
                        const int2 rg = range[rowbase + x];
                        for (int k = 0; k < rg.y; ++k) {
                            const float4 tt = pts[rg.x + k];
                            const float d = fmaf(m2x, tt.x,
                                            fmaf(m2y, tt.y,
                                            fmaf(m2z, tt.z, tt.w)));
                            minAcc = fminf(minAcc, d);
                        }
                    }
                }
            }
        }

        // lower bound on distance to any unscanned point
        float db = 3.4e38f;
        if (x0 > 0)     db = fminf(db, qf.x - (float)x0 * h);
        if (x1 < G - 1) db = fminf(db, (float)(x1 + 1) * h - qf.x);
        if (y0 > 0)     db = fminf(db, qf.y - (float)y0 * h);
        if (y1 < G - 1) db = fminf(db, (float)(y1 + 1) * h - qf.y);
        if (z0 > 0)     db = fminf(db, qf.z - (float)z0 * h);
        if (z1 < G - 1) db = fminf(db, (float)(z1 + 1) * h - qf.z);

        const bool full = (x0 == 0 && y0 == 0 && z0 == 0 &&
                           x1 == G - 1 && y1 == G - 1 && z1 == G - 1);
        const float dist = qn + minAcc;
        if (full || dist <= db * db) break;
        ++r;
    }

    g_dist[(size_t)yb * NPTS_MAX + oi] = fmaxf(qn + minAcc, 0.0f);
}

__global__ __launch_bounds__(RBLOCK)
void reduce_kernel(int N, int M, int B) {
    const int yb  = blockIdx.y;
    const int dir = yb / B;
    const int nQ  = dir ? M : N;
    const int q = blockIdx.x * blockDim.x + threadIdx.x;
    float v = (q < nQ) ? g_dist[(size_t)yb * NPTS_MAX + q] : 0.0f;
    __shared__ float red[RBLOCK / 32];
#pragma unroll
    for (int o = 16; o > 0; o >>= 1)
        v += __shfl_xor_sync(0xffffffffu, v, o);
    if ((threadIdx.x & 31) == 0) red[threadIdx.x >> 5] = v;
    __syncthreads();
    if (threadIdx.x == 0) {
        float s = 0.f;
#pragma unroll
        for (int w = 0; w < RBLOCK / 32; ++w) s += red[w];
        g_partials[(size_t)yb * gridDim.x + blockIdx.x] = s;
    }
}

__global__ void finalize_kernel(float* __restrict__ out, int out_size,
                                int N, int M, int B, int nbx) {
    float s0 = 0.f, s1 = 0.f;
    const int per_dir = B * nbx;
    for (int i = threadIdx.x; i < per_dir; i += blockDim.x) {
        s0 += g_partials[i];
        s1 += g_partials[per_dir + i];
    }
#pragma unroll
    for (int o = 16; o > 0; o >>= 1) {
        s0 += __shfl_xor_sync(0xffffffffu, s0, o);
        s1 += __shfl_xor_sync(0xffffffffu, s1, o);
    }
    __shared__ float r0[8], r1[8];
    const int nw = (blockDim.x + 31) >> 5;
    if ((threadIdx.x & 31) == 0) {
        r0[threadIdx.x >> 5] = s0;
        r1[threadIdx.x >> 5] = s1;
    }
    __syncthreads();
    if (threadIdx.x == 0) {
        float t0 = 0.f, t1 = 0.f;
        for (int w = 0; w < nw; ++w) { t0 += r0[w]; t1 += r1[w]; }
        const float rec = t0 / (float)((size_t)B * N) + t1 / (float)((size_t)B * M);
        for (int i = 0; i < out_size; ++i) out[i] = rec;  // (loss, rec_loss)
    }
}

extern "C" void kernel_launch(void* const* d_in, const int* in_sizes, int n_in,
                              void* d_out, int out_size) {
    const float* pos  = (const float*)d_in[0];
    const float* xhat = (const float*)d_in[1];

    const int B = 2;
    const int N = in_sizes[0] / (B * 3);
    const int M = in_sizes[1] / (B * 3);
    const int nsets = 2 * B;
    const int maxP  = (N > M) ? N : M;

    // 1. zero counts
    {
        const int n = nsets * NC;
        zero_kernel<<<(n + 255) / 256, 256>>>(n);
    }
    // 2. count
    {
        dim3 g((maxP + 255) / 256, nsets);
        count_kernel<<<g, 256>>>(pos, xhat, N, M, B);
    }
    // 3. scan
    scan_kernel<<<nsets, SCAN_T>>>();
    // 4. scatter
    {
        dim3 g((maxP + 255) / 256, nsets);
        scatter_kernel<<<g, 256>>>(pos, xhat, N, M, B);
    }
    // 5. query
    {
        dim3 g((maxP + QBLOCK - 1) / QBLOCK, nsets);
        query_kernel<<<g, QBLOCK>>>(N, M, B);
    }
    // 6. reduce
    const int nbx = (maxP + RBLOCK - 1) / RBLOCK;
    {
        dim3 g(nbx, nsets);
        reduce_kernel<<<g, RBLOCK>>>(N, M, B);
    }
    // 7. finalize
    finalize_kernel<<<1, 256>>>((float*)d_out, out_size, N, M, B, nbx);
}

// round 4
// speedup vs baseline: 1.0042x; 1.0042x over previous
#include <cuda_runtime.h>
#include <cuda_bf16.h>

// Chamfer distance via uniform spatial grid, B=2, N=M=8192, C=3, coords ~U[0,1).
// Pipeline (all graph-capturable, no allocation, static scratch):
//   1. zero cell counts
//   2. count points per cell (atomicAdd; counts deterministic)
//   3. per-set exclusive scan -> (start,count) ranges + scatter cursors
//   4. scatter points to cell-sorted order (float4 xyz+norm) + original index
//   5. query: for each sorted query, scan 3x3x3 ring (expand if needed),
//      min of (||t||^2 - 2 q.t); write dist to g_dist[original index]
//      (min is permutation-invariant -> bitwise deterministic output)
//   6. per-(dir,batch) fixed-order sum -> partials
//   7. finalize scalar
//
// d(q,t) = ||q||^2 + (||t||^2 - 2 q.t)

#define G        16
#define NC       (G * G * G)          // 4096 cells
#define B_MAX    4
#define NSETS    (2 * B_MAX)          // cloud * B + b
#define NPTS_MAX 8192
#define QBLOCK   128
#define RBLOCK   256

__device__ int    g_count [NSETS * NC];
__device__ int2   g_range [NSETS * NC];      // (start, count)
__device__ int    g_cursor[NSETS * NC];
__device__ float4 g_sorted[NSETS * NPTS_MAX]; // x,y,z,||p||^2  (cell-sorted)
__device__ int    g_sidx  [NSETS * NPTS_MAX]; // original index
__device__ float  g_dist  [NSETS * NPTS_MAX]; // [yb][orig index]
__device__ float  g_partials[NSETS * 64];

__device__ __forceinline__ int cell_of(float v) {
    int c = (int)(v * (float)G);
    return min(max(c, 0), G - 1);
}

__global__ void zero_kernel(int n) {
    int i = blockIdx.x * blockDim.x + threadIdx.x;
    if (i < n) g_count[i] = 0;
}

__global__ void count_kernel(const float* __restrict__ pos,
                             const float* __restrict__ xhat,
                             int N, int M, int B) {
    const int sid   = blockIdx.y;
    const int cloud = sid / B;
    const int b     = sid % B;
    const int n     = cloud ? M : N;
    const float* P  = cloud ? xhat : pos;
    const int i = blockIdx.x * blockDim.x + threadIdx.x;
    if (i >= n) return;
    const float* p = P + ((size_t)b * n + i) * 3;
    const int cell = (cell_of(p[2]) * G + cell_of(p[1])) * G + cell_of(p[0]);
    atomicAdd(&g_count[sid * NC + cell], 1);
}

#define SCAN_T 1024
#define CPT    (NC / SCAN_T)   // 4 cells per thread
__global__ __launch_bounds__(SCAN_T)
void scan_kernel() {
    const int sid  = blockIdx.x;
    const int base = sid * NC;
    const int tid  = threadIdx.x;
    int c[CPT];
    int tsum = 0;
#pragma unroll
    for (int j = 0; j < CPT; ++j) { c[j] = g_count[base + tid * CPT + j]; tsum += c[j]; }
    __shared__ int sc[SCAN_T];
    sc[tid] = tsum;
    __syncthreads();
    for (int off = 1; off < SCAN_T; off <<= 1) {
        int v = (tid >= off) ? sc[tid - off] : 0;
        __syncthreads();
        sc[tid] += v;
        __syncthreads();
    }
    int run = sc[tid] - tsum;   // exclusive prefix
#pragma unroll
    for (int j = 0; j < CPT; ++j) {
        g_range [base + tid * CPT + j] = make_int2(run, c[j]);
        g_cursor[base + tid * CPT + j] = run;
        run += c[j];
    }
}

__global__ void scatter_kernel(const float* __restrict__ pos,
                               const float* __restrict__ xhat,
                               int N, int M, int B) {
    const int sid   = blockIdx.y;
    const int cloud = sid / B;
    const int b     = sid % B;
    const int n     = cloud ? M : N;
    const float* P  = cloud ? xhat : pos;
    const int i = blockIdx.x * blockDim.x + threadIdx.x;
    if (i >= n) return;
    const float* p = P + ((size_t)b * n + i) * 3;
    const float x = p[0], y = p[1], z = p[2];
    const int cell = (cell_of(z) * G + cell_of(y)) * G + cell_of(x);
    const int idx  = atomicAdd(&g_cursor[sid * NC + cell], 1);
    g_sorted[sid * NPTS_MAX + idx] = make_float4(x, y, z, x * x + y * y + z * z);
    g_sidx  [sid * NPTS_MAX + idx] = i;
}

__global__ __launch_bounds__(QBLOCK)
void query_kernel(int N, int M, int B) {
    const int yb  = blockIdx.y;        // dir*B + b
    const int dir = yb / B;
    const int b   = yb % B;
    const int nQ  = dir ? M : N;
    const int sid_q = dir * B + b;            // queries: cloud == dir
    const int sid_t = (1 - dir) * B + b;      // targets: other cloud
    const int i = blockIdx.x * blockDim.x + threadIdx.x;
    if (i >= nQ) return;

    const float4 qf = g_sorted[sid_q * NPTS_MAX + i];
    const int    oi = g_sidx  [sid_q * NPTS_MAX + i];
    const float m2x = -2.0f * qf.x;
    const float m2y = -2.0f * qf.y;
    const float m2z = -2.0f * qf.z;
    const float qn  = qf.w;
    const int cx = cell_of(qf.x), cy = cell_of(qf.y), cz = cell_of(qf.z);

    const int2*   __restrict__ range = g_range  + sid_t * NC;
    const float4* __restrict__ pts   = g_sorted + sid_t * NPTS_MAX;

    const float h = 1.0f / (float)G;
    float minAcc = 3.4e38f;
    int r = 1;

    while (true) {
        const int x0 = max(cx - r, 0), x1 = min(cx + r, G - 1);
        const int y0 = max(cy - r, 0), y1 = min(cy + r, G - 1);
        const int z0 = max(cz - r, 0), z1 = min(cz + r, G - 1);

        for (int z = z0; z <= z1; ++z) {
            const int dz = abs(z - cz);
            for (int y = y0; y <= y1; ++y) {
                const int dyz = max(abs(y - cy), dz);
                const int rowbase = (z * G + y) * G;
                if (r > 1 && dyz < r) {
                    // interior rows already scanned; only the two x extremes are new
#pragma unroll
                    for (int t = 0; t < 2; ++t) {
                        const int x = (t == 0) ? (cx - r) : (cx + r);
                        if (x < 0 || x > G - 1) continue;
                        const int2 rg = range[rowbase + x];
                        for (int k = 0; k < rg.y; ++k) {
                            const float4 tt = pts[rg.x + k];
                            const float d = fmaf(m2x, tt.x,
                                            fmaf(m2y, tt.y,
                                            fmaf(m2z, tt.z, tt.w)));
                            minAcc = fminf(minAcc, d);
                        }
                    }
                } else {
                    for (int x = x0; x <= x1; ++x) {
                        const int2 rg = range[rowbase + x];
                        for (int k = 0; k < rg.y; ++k) {
                            const float4 tt = pts[rg.x + k];
                            const float d = fmaf(m2x, tt.x,
                                            fmaf(m2y, tt.y,
                                            fmaf(m2z, tt.z, tt.w)));
                            minAcc = fminf(minAcc, d);
                        }
                    }
                }
            }
        }

        // lower bound on distance to any unscanned point
        float db = 3.4e38f;
        if (x0 > 0)     db = fminf(db, qf.x - (float)x0 * h);
        if (x1 < G - 1) db = fminf(db, (float)(x1 + 1) * h - qf.x);
        if (y0 > 0)     db = fminf(db, qf.y - (float)y0 * h);
        if (y1 < G - 1) db = fminf(db, (float)(y1 + 1) * h - qf.y);
        if (z0 > 0)     db = fminf(db, qf.z - (float)z0 * h);
        if (z1 < G - 1) db = fminf(db, (float)(z1 + 1) * h - qf.z);

        const bool full = (x0 == 0 && y0 == 0 && z0 == 0 &&
                           x1 == G - 1 && y1 == G - 1 && z1 == G - 1);
        const float dist = qn + minAcc;
        if (full || dist <= db * db) break;
        ++r;
    }

    g_dist[(size_t)yb * NPTS_MAX + oi] = fmaxf(qn + minAcc, 0.0f);
}

__global__ __launch_bounds__(RBLOCK)
void reduce_kernel(int N, int M, int B) {
    const int yb  = blockIdx.y;
    const int dir = yb / B;
    const int nQ  = dir ? M : N;
    const int q = blockIdx.x * blockDim.x + threadIdx.x;
    float v = (q < nQ) ? g_dist[(size_t)yb * NPTS_MAX + q] : 0.0f;
    __shared__ float red[RBLOCK / 32];
#pragma unroll
    for (int o = 16; o > 0; o >>= 1)
        v += __shfl_xor_sync(0xffffffffu, v, o);
    if ((threadIdx.x & 31) == 0) red[threadIdx.x >> 5] = v;
    __syncthreads();
    if (threadIdx.x == 0) {
        float s = 0.f;
#pragma unroll
        for (int w = 0; w < RBLOCK / 32; ++w) s += red[w];
        g_partials[(size_t)yb * gridDim.x + blockIdx.x] = s;
    }
}

__global__ void finalize_kernel(float* __restrict__ out, int out_size,
                                int N, int M, int B, int nbx) {
    float s0 = 0.f, s1 = 0.f;
    const int per_dir = B * nbx;
    for (int i = threadIdx.x; i < per_dir; i += blockDim.x) {
        s0 += g_partials[i];
        s1 += g_partials[per_dir + i];
    }
#pragma unroll
    for (int o = 16; o > 0; o >>= 1) {
        s0 += __shfl_xor_sync(0xffffffffu, s0, o);
        s1 += __shfl_xor_sync(0xffffffffu, s1, o);
    }
    __shared__ float r0[8], r1[8];
    const int nw = (blockDim.x + 31) >> 5;
    if ((threadIdx.x & 31) == 0) {
        r0[threadIdx.x >> 5] = s0;
        r1[threadIdx.x >> 5] = s1;
    }
    __syncthreads();
    if (threadIdx.x == 0) {
        float t0 = 0.f, t1 = 0.f;
        for (int w = 0; w < nw; ++w) { t0 += r0[w]; t1 += r1[w]; }
        const float rec = t0 / (float)((size_t)B * N) + t1 / (float)((size_t)B * M);
        for (int i = 0; i < out_size; ++i) out[i] = rec;  // (loss, rec_loss)
    }
}

extern "C" void kernel_launch(void* const* d_in, const int* in_sizes, int n_in,
                              void* d_out, int out_size) {
    const float* pos  = (const float*)d_in[0];
    const float* xhat = (const float*)d_in[1];

    const int B = 2;
    const int N = in_sizes[0] / (B * 3);
    const int M = in_sizes[1] / (B * 3);
    const int nsets = 2 * B;
    const int maxP  = (N > M) ? N : M;

    // 1. zero counts
    {
        const int n = nsets * NC;
        zero_kernel<<<(n + 255) / 256, 256>>>(n);
    }
    // 2. count
    {
        dim3 g((maxP + 255) / 256, nsets);
        count_kernel<<<g, 256>>>(pos, xhat, N, M, B);
    }
    // 3. scan
    scan_kernel<<<nsets, SCAN_T>>>();
    // 4. scatter
    {
        dim3 g((maxP + 255) / 256, nsets);
        scatter_kernel<<<g, 256>>>(pos, xhat, N, M, B);
    }
    // 5. query
    {
        dim3 g((maxP + QBLOCK - 1) / QBLOCK, nsets);
        query_kernel<<<g, QBLOCK>>>(N, M, B);
    }
    // 6. reduce
    const int nbx = (maxP + RBLOCK - 1) / RBLOCK;
    {
        dim3 g(nbx, nsets);
        reduce_kernel<<<g, RBLOCK>>>(N, M, B);
    }
    // 7. finalize
    finalize_kernel<<<1, 256>>>((float*)d_out, out_size, N, M, B, nbx);
}